// round 6
// baseline (speedup 1.0000x reference)
#include <cuda_runtime.h>
#include <cstdint>

#define DIM   64
#define NPAD  53248          // 1024 * 52 (>= N, padded for single-block scan)
#define EMAX  800000

// Scratch (allocation-free rule: __device__ globals).
// g_deg is zero on first call (static init) and re-zeroed by k_fused at the
// end of every launch -> invariant holds across graph replays (deterministic).
__device__ int g_deg[NPAD];
__device__ int g_start[NPAD];
__device__ int g_cursor[NPAD];
__device__ int g_cols[EMAX];

// ---------------------------------------------------------------------------
// 1. histogram of destination rows (4 edges per thread, int4 reads)
// ---------------------------------------------------------------------------
__global__ __launch_bounds__(256) void k_hist(const int* __restrict__ ei, int E) {
    int i = (blockIdx.x * blockDim.x + threadIdx.x) * 4;
    if (i + 3 < E) {
        int4 r = *(const int4*)(ei + i);
        atomicAdd(&g_deg[r.x], 1);
        atomicAdd(&g_deg[r.y], 1);
        atomicAdd(&g_deg[r.z], 1);
        atomicAdd(&g_deg[r.w], 1);
    } else {
        for (int k = i; k < E; k++) atomicAdd(&g_deg[ei[k]], 1);
    }
}

// ---------------------------------------------------------------------------
// 2. single-block exclusive scan over all NPAD degrees -> start, cursor.
//    1024 threads x 52 ints (13 int4 loads), two-pass (re-read, L1/L2 hot).
// ---------------------------------------------------------------------------
__global__ __launch_bounds__(1024) void k_scan() {
    __shared__ int s[1024];
    int tid = threadIdx.x;
    const int4* dv = (const int4*)g_deg + tid * 13;

    int tot = 0;
    #pragma unroll
    for (int i = 0; i < 13; i++) {
        int4 v = dv[i];
        tot += v.x + v.y + v.z + v.w;
    }
    s[tid] = tot;
    __syncthreads();
    #pragma unroll
    for (int off = 1; off < 1024; off <<= 1) {
        int t = (tid >= off) ? s[tid - off] : 0;
        __syncthreads();
        s[tid] += t;
        __syncthreads();
    }
    int run = s[tid] - tot;     // exclusive prefix of this thread's chunk

    int4* sv = (int4*)g_start  + tid * 13;
    int4* cv = (int4*)g_cursor + tid * 13;
    #pragma unroll
    for (int i = 0; i < 13; i++) {
        int4 v = dv[i];
        int4 o;
        o.x = run; run += v.x;
        o.y = run; run += v.y;
        o.z = run; run += v.z;
        o.w = run; run += v.w;
        sv[i] = o;
        cv[i] = o;
    }
}

// ---------------------------------------------------------------------------
// 3. scatter source cols into CSR order (4 edges per thread, int4 reads)
// ---------------------------------------------------------------------------
__global__ __launch_bounds__(256) void k_scatter(const int* __restrict__ ei, int E) {
    int i = (blockIdx.x * blockDim.x + threadIdx.x) * 4;
    if (i + 3 < E) {
        int4 r = *(const int4*)(ei + i);
        int4 c = *(const int4*)(ei + E + i);
        g_cols[atomicAdd(&g_cursor[r.x], 1)] = c.x;
        g_cols[atomicAdd(&g_cursor[r.y], 1)] = c.y;
        g_cols[atomicAdd(&g_cursor[r.z], 1)] = c.z;
        g_cols[atomicAdd(&g_cursor[r.w], 1)] = c.w;
    } else {
        for (int k = i; k < E; k++)
            g_cols[atomicAdd(&g_cursor[ei[k]], 1)] = ei[E + k];
    }
}

// ---------------------------------------------------------------------------
// 4. fused gather + normalize + GEMM + deg-reset.
//    Block = 64 nodes, 256 threads.
//    Phase A: 16 threads/row gather neighbor float4 sums -> sA (normalized).
//    Phase B: register-blocked 4x4 GEMM vs W^T, + bias, store out.
// ---------------------------------------------------------------------------
__global__ __launch_bounds__(256) void k_fused(
    const float* __restrict__ x,
    const float* __restrict__ W,   // [64 out][64 in] row-major
    const float* __restrict__ b,   // [64]
    float* __restrict__ out,       // [n][64]
    int n)
{
    __shared__ float sW[64 * 68];  // sW[k*68+j] = W[j][k]
    __shared__ float sA[64 * 68];  // normalized agg tile
    __shared__ float sB[64];

    const int tid  = threadIdx.x;
    const int base = blockIdx.x * 64;

    // Load W transposed + bias
    for (int idx = tid; idx < 64 * 64; idx += 256) {
        int j = idx >> 6;
        int k = idx & 63;
        sW[k * 68 + j] = W[idx];
    }
    if (tid < 64) sB[tid] = b[tid];

    // ---- Phase A: gather ----
    const int t  = tid & 15;       // float4 chunk
    const int rg = tid >> 4;       // row-group lane 0..15
    #pragma unroll
    for (int pass = 0; pass < 4; pass++) {
        int rl  = pass * 16 + rg;  // local row 0..63
        int row = base + rl;
        float4 acc = make_float4(0.f, 0.f, 0.f, 0.f);
        float  inv = 0.f;
        if (row < n) {
            int s0 = g_start[row];
            int c  = g_deg[row];
            int j = 0;
            for (; j + 4 <= c; j += 4) {
                int c0 = g_cols[s0 + j + 0];
                int c1 = g_cols[s0 + j + 1];
                int c2 = g_cols[s0 + j + 2];
                int c3 = g_cols[s0 + j + 3];
                float4 v0 = *(const float4*)(x + (size_t)c0 * DIM + t * 4);
                float4 v1 = *(const float4*)(x + (size_t)c1 * DIM + t * 4);
                float4 v2 = *(const float4*)(x + (size_t)c2 * DIM + t * 4);
                float4 v3 = *(const float4*)(x + (size_t)c3 * DIM + t * 4);
                acc.x += v0.x + v1.x + v2.x + v3.x;
                acc.y += v0.y + v1.y + v2.y + v3.y;
                acc.z += v0.z + v1.z + v2.z + v3.z;
                acc.w += v0.w + v1.w + v2.w + v3.w;
            }
            for (; j < c; j++) {
                int cc = g_cols[s0 + j];
                float4 v = *(const float4*)(x + (size_t)cc * DIM + t * 4);
                acc.x += v.x; acc.y += v.y; acc.z += v.z; acc.w += v.w;
            }
            inv = 1.0f / ((float)c + 1e-6f);
            if (t == 0) g_deg[row] = 0;   // reset for next launch (c consumed)
        }
        acc.x *= inv; acc.y *= inv; acc.z *= inv; acc.w *= inv;
        *(float4*)&sA[rl * 68 + t * 4] = acc;
    }
    __syncthreads();

    // ---- Phase B: GEMM ----
    const int tx = tid & 15;   // 4 cols at tx*4
    const int ty = tid >> 4;   // 4 nodes at ty*4

    float acc[4][4];
    #pragma unroll
    for (int i = 0; i < 4; i++)
        #pragma unroll
        for (int c = 0; c < 4; c++)
            acc[i][c] = 0.f;

    #pragma unroll
    for (int k = 0; k < 64; k += 4) {
        float4 wv0 = *(const float4*)&sW[(k + 0) * 68 + tx * 4];
        float4 wv1 = *(const float4*)&sW[(k + 1) * 68 + tx * 4];
        float4 wv2 = *(const float4*)&sW[(k + 2) * 68 + tx * 4];
        float4 wv3 = *(const float4*)&sW[(k + 3) * 68 + tx * 4];
        #pragma unroll
        for (int i = 0; i < 4; i++) {
            float4 av = *(const float4*)&sA[(ty * 4 + i) * 68 + k];
            acc[i][0] += av.x * wv0.x + av.y * wv1.x + av.z * wv2.x + av.w * wv3.x;
            acc[i][1] += av.x * wv0.y + av.y * wv1.y + av.z * wv2.y + av.w * wv3.y;
            acc[i][2] += av.x * wv0.z + av.y * wv1.z + av.z * wv2.z + av.w * wv3.z;
            acc[i][3] += av.x * wv0.w + av.y * wv1.w + av.z * wv2.w + av.w * wv3.w;
        }
    }

    #pragma unroll
    for (int i = 0; i < 4; i++) {
        int node = base + ty * 4 + i;
        if (node < n) {
            float4 o;
            o.x = acc[i][0] + sB[tx * 4 + 0];
            o.y = acc[i][1] + sB[tx * 4 + 1];
            o.z = acc[i][2] + sB[tx * 4 + 2];
            o.w = acc[i][3] + sB[tx * 4 + 3];
            *(float4*)&out[(size_t)node * DIM + tx * 4] = o;
        }
    }
}

// ---------------------------------------------------------------------------
// kernel_launch — inputs: x [N*64 f32], edge_index [2*E i32], W [64*64 f32],
// b [64 f32]; output [N*64 f32].
// ---------------------------------------------------------------------------
extern "C" void kernel_launch(void* const* d_in, const int* in_sizes, int n_in,
                              void* d_out, int out_size) {
    const float* x  = (const float*)d_in[0];
    const int*   ei = (const int*)d_in[1];
    const float* W  = (const float*)d_in[2];
    const float* b  = (const float*)d_in[3];
    float*       out = (float*)d_out;

    int n = in_sizes[0] / DIM;       // 50000
    int E = in_sizes[1] / 2;         // 800000

    int eblocks = (E / 4 + 255) / 256 + 1;   // 4 edges per thread (+ tail safety)

    k_hist<<<eblocks, 256>>>(ei, E);
    k_scan<<<1, 1024>>>();
    k_scatter<<<eblocks, 256>>>(ei, E);
    k_fused<<<(n + 63) / 64, 256>>>(x, W, b, out, n);
}